// round 3
// baseline (speedup 1.0000x reference)
#include <cuda_runtime.h>
#include <cuda_bf16.h>
#include <cstdint>

#define NN   50000
#define FD   128
#define RR   3
#define EE   800000
#define OUTD 64

// ---------------- static device scratch (no runtime allocation) ----------------
__device__ float g_h0[(size_t)NN * FD];
__device__ float g_h1[(size_t)NN * FD];
__device__ float g_agg[(size_t)RR * NN * FD];
__device__ int   g_rowptr[RR * (NN + 1)];
__device__ int   g_fill[RR * NN];
__device__ int   g_outdeg[RR * NN];
__device__ int   g_indeg[RR * NN];
__device__ int   g_srcoff[(size_t)RR * EE];   // src*FD, CSR-ordered by dst
__device__ float g_coef[(size_t)RR * EE];     // norm coef (incl. 1/3 mean fold)

// ---------------- degree histogram ----------------
__global__ void k_degree(const int* __restrict__ src, const int* __restrict__ dst) {
    int e = blockIdx.x * blockDim.x + threadIdx.x;
    int r = blockIdx.y;
    if (e < EE) {
        atomicAdd(&g_outdeg[r * NN + src[(size_t)r * EE + e]], 1);
        atomicAdd(&g_indeg [r * NN + dst[(size_t)r * EE + e]], 1);
    }
}

// ---------------- exclusive scan of in-degree -> rowptr (one block / relation) ----------------
__global__ void k_scan() {
    int r = blockIdx.x, t = threadIdx.x, lane = t & 31, wid = t >> 5;
    __shared__ int wsum[32];
    __shared__ int s_off;
    if (t == 0) s_off = 0;
    __syncthreads();
    for (int base = 0; base < NN; base += 1024) {
        int idx = base + t;
        int v = (idx < NN) ? g_indeg[r * NN + idx] : 0;
        int incl = v;
        #pragma unroll
        for (int s = 1; s < 32; s <<= 1) {
            int u = __shfl_up_sync(0xffffffffu, incl, s);
            if (lane >= s) incl += u;
        }
        if (lane == 31) wsum[wid] = incl;
        __syncthreads();
        if (wid == 0) {
            int w = wsum[lane];
            int wi = w;
            #pragma unroll
            for (int s = 1; s < 32; s <<= 1) {
                int u = __shfl_up_sync(0xffffffffu, wi, s);
                if (lane >= s) wi += u;
            }
            wsum[lane] = wi - w;   // exclusive warp prefix
        }
        __syncthreads();
        if (idx < NN) g_rowptr[r * (NN + 1) + idx] = s_off + wsum[wid] + incl - v;
        __syncthreads();
        if (t == 1023) s_off += wsum[31] + incl;   // grand total of this chunk
        __syncthreads();
    }
    if (t == 0) g_rowptr[r * (NN + 1) + NN] = s_off;
}

// ---------------- counting-sort fill: CSR by dst + edge coefficient ----------------
__global__ void k_fill(const int* __restrict__ src, const int* __restrict__ dst) {
    int e = blockIdx.x * blockDim.x + threadIdx.x;
    int r = blockIdx.y;
    if (e < EE) {
        int s = src[(size_t)r * EE + e];
        int d = dst[(size_t)r * EE + e];
        int pos = g_rowptr[r * (NN + 1) + d] + atomicAdd(&g_fill[r * NN + d], 1);
        float no = rsqrtf(fmaxf((float)g_outdeg[r * NN + s], 1.f));
        float ni = rsqrtf(fmaxf((float)g_indeg [r * NN + d], 1.f));
        g_srcoff[(size_t)r * EE + pos] = s * FD;
        g_coef  [(size_t)r * EE + pos] = no * ni * (1.f / 3.f);
    }
}

// ---------------- SpMM: per-dst-row gather-sum (no fp atomics) ----------------
template <int RPB>
__global__ __launch_bounds__(FD) void k_spmm(const float* __restrict__ h,
                                             float* __restrict__ agg) {
    int r = blockIdx.y;
    int t = threadIdx.x;               // feature column
    int row0 = blockIdx.x * RPB;
    const int*   si = &g_srcoff[(size_t)r * EE];
    const float* cf = &g_coef  [(size_t)r * EE];
    #pragma unroll
    for (int i = 0; i < RPB; i++) {
        int row = row0 + i;
        if (row >= NN) return;
        int beg = g_rowptr[r * (NN + 1) + row];
        int end = g_rowptr[r * (NN + 1) + row + 1];
        float acc = 0.f;
        int e = beg;
        for (; e + 3 < end; e += 4) {     // MLP=4 gather
            int   o0 = si[e], o1 = si[e + 1], o2 = si[e + 2], o3 = si[e + 3];
            float c0 = cf[e], c1 = cf[e + 1], c2 = cf[e + 2], c3 = cf[e + 3];
            acc += c0 * __ldg(&h[o0 + t]);
            acc += c1 * __ldg(&h[o1 + t]);
            acc += c2 * __ldg(&h[o2 + t]);
            acc += c3 * __ldg(&h[o3 + t]);
        }
        for (; e < end; e++) acc += cf[e] * __ldg(&h[si[e] + t]);
        agg[(size_t)r * NN * FD + (size_t)row * FD + t] = acc;
    }
}

// ---------------- tiled fp32 GEMM, bias + optional leaky-relu epilogue ----------------
// A(row,k) = A[(k>>7)*NN*FD + row*FD + (k&127)]   (relation-chunked concat)
// B is row-major [K, BN]; C is row-major [M, BN].
template <int BM, int BN, int BK, int TM, int TN, int NREL, bool RELU>
__global__ __launch_bounds__(256) void k_gemm(const float* __restrict__ A,
                                              const float* __restrict__ B,
                                              const float* __restrict__ bias,
                                              float* __restrict__ C,
                                              int M, int K) {
    __shared__ float As[BK][BM + 1];
    __shared__ float Bs[BK][BN];
    const int t = threadIdx.x;                 // 256 threads
    const int tx = t % (BN / TN);              // 16
    const int ty = t / (BN / TN);              // 16
    const int blockRow = blockIdx.x * BM;

    float acc[TM][TN];
    #pragma unroll
    for (int i = 0; i < TM; i++)
        #pragma unroll
        for (int j = 0; j < TN; j++) acc[i][j] = 0.f;

    const int aK = t % BK;                     // k within tile
    const int aR = t / BK;                     // row base (0..15)
    constexpr int ASTRIDE = 256 / BK;          // 16 rows per pass
    const int bC = t % BN;
    const int bR0 = t / BN;
    constexpr int BSTRIDE = 256 / BN;

    for (int k0 = 0; k0 < K; k0 += BK) {
        #pragma unroll
        for (int i = 0; i < BM / ASTRIDE; i++) {
            int row = blockRow + aR + i * ASTRIDE;
            int k = k0 + aK;
            float v = 0.f;
            if (row < M)
                v = A[(size_t)(k >> 7) * ((size_t)NN * FD) + (size_t)row * FD + (k & 127)];
            As[aK][aR + i * ASTRIDE] = v;
        }
        #pragma unroll
        for (int i = 0; i < BK / BSTRIDE; i++) {
            int k = k0 + bR0 + i * BSTRIDE;
            Bs[bR0 + i * BSTRIDE][bC] = B[(size_t)k * BN + bC];
        }
        __syncthreads();
        #pragma unroll
        for (int kk = 0; kk < BK; kk++) {
            float ra[TM], rb[TN];
            #pragma unroll
            for (int i = 0; i < TM; i++) ra[i] = As[kk][ty * TM + i];
            #pragma unroll
            for (int j = 0; j < TN; j++) rb[j] = Bs[kk][tx * TN + j];
            #pragma unroll
            for (int i = 0; i < TM; i++)
                #pragma unroll
                for (int j = 0; j < TN; j++) acc[i][j] += ra[i] * rb[j];
        }
        __syncthreads();
    }

    float bj[TN];
    #pragma unroll
    for (int j = 0; j < TN; j++) {
        int col = tx * TN + j;
        if (NREL == 3)
            bj[j] = (bias[col] + bias[FD + col] + bias[2 * FD + col]) * (1.f / 3.f);
        else
            bj[j] = bias[col];
    }
    #pragma unroll
    for (int i = 0; i < TM; i++) {
        int row = blockRow + ty * TM + i;
        if (row < M) {
            #pragma unroll
            for (int j = 0; j < TN; j++) {
                int col = tx * TN + j;
                float v = acc[i][j] + bj[j];
                if (RELU) v = (v > 0.f) ? v : 0.01f * v;
                C[(size_t)row * BN + col] = v;
            }
        }
    }
}

// ---------------- launch ----------------
extern "C" void kernel_launch(void* const* d_in, const int* in_sizes, int n_in,
                              void* d_out, int out_size) {
    const float* x    = (const float*)d_in[0];
    const int*   esrc = (const int*)  d_in[1];
    const int*   edst = (const int*)  d_in[2];
    const float* W0   = (const float*)d_in[3];
    const float* b0   = (const float*)d_in[4];
    const float* Wl   = (const float*)d_in[5];
    const float* bl   = (const float*)d_in[6];
    const float* Wout = (const float*)d_in[7];
    const float* bout = (const float*)d_in[8];
    float* out = (float*)d_out;

    void *p_od, *p_id, *p_fl, *p_h0, *p_h1, *p_agg;
    cudaGetSymbolAddress(&p_od, g_outdeg);
    cudaGetSymbolAddress(&p_id, g_indeg);
    cudaGetSymbolAddress(&p_fl, g_fill);
    cudaGetSymbolAddress(&p_h0, g_h0);
    cudaGetSymbolAddress(&p_h1, g_h1);
    cudaGetSymbolAddress(&p_agg, g_agg);

    cudaMemsetAsync(p_od, 0, sizeof(int) * RR * NN);
    cudaMemsetAsync(p_id, 0, sizeof(int) * RR * NN);
    cudaMemsetAsync(p_fl, 0, sizeof(int) * RR * NN);

    dim3 ge((EE + 255) / 256, RR);
    k_degree<<<ge, 256>>>(esrc, edst);
    k_scan<<<RR, 1024>>>();
    k_fill<<<ge, 256>>>(esrc, edst);

    float* hbuf[2] = { (float*)p_h0, (float*)p_h1 };
    float* agg = (float*)p_agg;
    const float* cur = x;

    const int RPB = 4;
    dim3 gs((NN + RPB - 1) / RPB, RR);
    const int GB = (NN + 127) / 128;   // 391

    for (int l = 0; l < 5; l++) {
        k_spmm<RPB><<<gs, FD>>>(cur, agg);
        const float* W = (l == 0) ? W0 : (Wl + (size_t)(l - 1) * RR * FD * FD);
        const float* b = (l == 0) ? b0 : (bl + (size_t)(l - 1) * RR * FD);
        float* hout = hbuf[l & 1];
        if (l < 4)
            k_gemm<128, 128, 16, 8, 8, 3, true ><<<GB, 256>>>(agg, W, b, hout, NN, RR * FD);
        else
            k_gemm<128, 128, 16, 8, 8, 3, false><<<GB, 256>>>(agg, W, b, hout, NN, RR * FD);
        cur = hout;
    }

    k_gemm<128, OUTD, 16, 8, 4, 1, false><<<GB, 256>>>(cur, Wout, bout, out, NN, FD);
}

// round 5
// speedup vs baseline: 2.1111x; 2.1111x over previous
#include <cuda_runtime.h>
#include <cuda_bf16.h>
#include <cstdint>

#define NN   50000
#define NP   50128           // padded rows (OOB-safe cp.async for last block)
#define FD   128
#define RR   3
#define EE   800000
#define OUTD 64
#define NNFD ((size_t)NN * FD)

// ---------------- static device scratch ----------------
__device__ float4 g_h0[NNFD / 4];
__device__ float4 g_h1[NNFD / 4];
__device__ uint2  g_aggh[(size_t)RR * NP * 32];   // bf16 hi image of agg [r][row][128]
__device__ uint2  g_aggl[(size_t)RR * NP * 32];   // bf16 lo image
__device__ uint32_t g_hbh[(size_t)NP * 64];       // bf16 hi of layer-4 output [row][128]
__device__ uint32_t g_hbl[(size_t)NP * 64];
__device__ __nv_bfloat16 g_wh[RR * FD * FD];      // weight hi (row-major [K][N])
__device__ __nv_bfloat16 g_wl[RR * FD * FD];
__device__ int    g_rowptr[RR * (NN + 1)];
__device__ int    g_fill[RR * NN];
__device__ int    g_outdeg[RR * NN];
__device__ int    g_indeg[RR * NN];
__device__ int    g_srcoff[(size_t)RR * EE];      // src*32 (float4 units), CSR-ordered by dst
__device__ float  g_coef[(size_t)RR * EE];        // norm coef (incl. 1/3 mean fold)

// ---------------- ptx helpers (baseline PTX only — no sm_103a-specific features) ----------------
__device__ __forceinline__ uint32_t smem_u32(const void* p) {
    uint32_t a;
    asm("{ .reg .u64 t; cvta.to.shared.u64 t, %1; cvt.u32.u64 %0, t; }" : "=r"(a) : "l"(p));
    return a;
}
__device__ __forceinline__ void cpasync16(uint32_t sdst, const void* gsrc) {
    asm volatile("cp.async.cg.shared.global [%0], [%1], 16;" :: "r"(sdst), "l"(gsrc) : "memory");
}
__device__ __forceinline__ void cp_commit() {
    asm volatile("cp.async.commit_group;" ::: "memory");
}
template <int N>
__device__ __forceinline__ void cp_wait() {
    asm volatile("cp.async.wait_group %0;" :: "n"(N) : "memory");
}
__device__ __forceinline__ void ldsm_x4(uint32_t* r, uint32_t addr) {
    asm volatile("ldmatrix.sync.aligned.m8n8.x4.shared.b16 {%0,%1,%2,%3}, [%4];"
                 : "=r"(r[0]), "=r"(r[1]), "=r"(r[2]), "=r"(r[3]) : "r"(addr));
}
__device__ __forceinline__ void ldsm_x4t(uint32_t* r, uint32_t addr) {
    asm volatile("ldmatrix.sync.aligned.m8n8.x4.trans.shared.b16 {%0,%1,%2,%3}, [%4];"
                 : "=r"(r[0]), "=r"(r[1]), "=r"(r[2]), "=r"(r[3]) : "r"(addr));
}
__device__ __forceinline__ void mma16816(float* d, const uint32_t* a, const uint32_t* b) {
    asm volatile("mma.sync.aligned.m16n8k16.row.col.f32.bf16.bf16.f32 "
                 "{%0,%1,%2,%3},{%4,%5,%6,%7},{%8,%9},{%0,%1,%2,%3};"
                 : "+f"(d[0]), "+f"(d[1]), "+f"(d[2]), "+f"(d[3])
                 : "r"(a[0]), "r"(a[1]), "r"(a[2]), "r"(a[3]), "r"(b[0]), "r"(b[1]));
}

// ---------------- degree histogram ----------------
__global__ void k_degree(const int* __restrict__ src, const int* __restrict__ dst) {
    int e = blockIdx.x * blockDim.x + threadIdx.x;
    int r = blockIdx.y;
    if (e < EE) {
        atomicAdd(&g_outdeg[r * NN + src[(size_t)r * EE + e]], 1);
        atomicAdd(&g_indeg [r * NN + dst[(size_t)r * EE + e]], 1);
    }
}

// ---------------- exclusive scan of in-degree -> rowptr ----------------
__global__ void k_scan() {
    int r = blockIdx.x, t = threadIdx.x, lane = t & 31, wid = t >> 5;
    __shared__ int wsum[32];
    __shared__ int s_off;
    if (t == 0) s_off = 0;
    __syncthreads();
    for (int base = 0; base < NN; base += 1024) {
        int idx = base + t;
        int v = (idx < NN) ? g_indeg[r * NN + idx] : 0;
        int incl = v;
        #pragma unroll
        for (int s = 1; s < 32; s <<= 1) {
            int u = __shfl_up_sync(0xffffffffu, incl, s);
            if (lane >= s) incl += u;
        }
        if (lane == 31) wsum[wid] = incl;
        __syncthreads();
        if (wid == 0) {
            int w = wsum[lane];
            int wi = w;
            #pragma unroll
            for (int s = 1; s < 32; s <<= 1) {
                int u = __shfl_up_sync(0xffffffffu, wi, s);
                if (lane >= s) wi += u;
            }
            wsum[lane] = wi - w;
        }
        __syncthreads();
        if (idx < NN) g_rowptr[r * (NN + 1) + idx] = s_off + wsum[wid] + incl - v;
        __syncthreads();
        if (t == 1023) s_off += wsum[31] + incl;
        __syncthreads();
    }
    if (t == 0) g_rowptr[r * (NN + 1) + NN] = s_off;
}

// ---------------- counting-sort fill: CSR by dst + edge coefficient ----------------
__global__ void k_fill(const int* __restrict__ src, const int* __restrict__ dst) {
    int e = blockIdx.x * blockDim.x + threadIdx.x;
    int r = blockIdx.y;
    if (e < EE) {
        int s = src[(size_t)r * EE + e];
        int d = dst[(size_t)r * EE + e];
        int pos = g_rowptr[r * (NN + 1) + d] + atomicAdd(&g_fill[r * NN + d], 1);
        float no = rsqrtf(fmaxf((float)g_outdeg[r * NN + s], 1.f));
        float ni = rsqrtf(fmaxf((float)g_indeg [r * NN + d], 1.f));
        g_srcoff[(size_t)r * EE + pos] = s * 32;      // float4 units
        g_coef  [(size_t)r * EE + pos] = no * ni * (1.f / 3.f);
    }
}

// ---------------- SpMM: warp-per-row float4 gathers; epilogue emits bf16 hi/lo ----------------
__global__ __launch_bounds__(256) void k_spmm(const float4* __restrict__ h4,
                                              uint2* __restrict__ aggh,
                                              uint2* __restrict__ aggl) {
    int r = blockIdx.y;
    int row = blockIdx.x * 8 + (threadIdx.x >> 5);
    int lane = threadIdx.x & 31;
    if (row >= NN) return;
    int beg = g_rowptr[r * (NN + 1) + row];
    int end = g_rowptr[r * (NN + 1) + row + 1];
    const int*   si = &g_srcoff[(size_t)r * EE];
    const float* cf = &g_coef  [(size_t)r * EE];
    float4 acc = {0.f, 0.f, 0.f, 0.f};
    int e = beg;
    for (; e + 4 <= end; e += 4) {
        int   o0 = __ldg(&si[e]),     o1 = __ldg(&si[e + 1]);
        int   o2 = __ldg(&si[e + 2]), o3 = __ldg(&si[e + 3]);
        float c0 = __ldg(&cf[e]),     c1 = __ldg(&cf[e + 1]);
        float c2 = __ldg(&cf[e + 2]), c3 = __ldg(&cf[e + 3]);
        float4 v0 = __ldg(&h4[o0 + lane]);
        float4 v1 = __ldg(&h4[o1 + lane]);
        float4 v2 = __ldg(&h4[o2 + lane]);
        float4 v3 = __ldg(&h4[o3 + lane]);
        acc.x += c0 * v0.x + c1 * v1.x + c2 * v2.x + c3 * v3.x;
        acc.y += c0 * v0.y + c1 * v1.y + c2 * v2.y + c3 * v3.y;
        acc.z += c0 * v0.z + c1 * v1.z + c2 * v2.z + c3 * v3.z;
        acc.w += c0 * v0.w + c1 * v1.w + c2 * v2.w + c3 * v3.w;
    }
    for (; e < end; e++) {
        float c = __ldg(&cf[e]);
        float4 v = __ldg(&h4[__ldg(&si[e]) + lane]);
        acc.x += c * v.x; acc.y += c * v.y; acc.z += c * v.z; acc.w += c * v.w;
    }
    // split into bf16 hi/lo and store (4 bf16 = one uint2 per stream)
    __nv_bfloat162 h01(__float2bfloat16(acc.x), __float2bfloat16(acc.y));
    __nv_bfloat162 h23(__float2bfloat16(acc.z), __float2bfloat16(acc.w));
    __nv_bfloat162 l01(__float2bfloat16(acc.x - __bfloat162float(h01.x)),
                       __float2bfloat16(acc.y - __bfloat162float(h01.y)));
    __nv_bfloat162 l23(__float2bfloat16(acc.z - __bfloat162float(h23.x)),
                       __float2bfloat16(acc.w - __bfloat162float(h23.y)));
    size_t idx = ((size_t)r * NP + row) * 32 + lane;
    uint2 hv = { *reinterpret_cast<uint32_t*>(&h01), *reinterpret_cast<uint32_t*>(&h23) };
    uint2 lv = { *reinterpret_cast<uint32_t*>(&l01), *reinterpret_cast<uint32_t*>(&l23) };
    aggh[idx] = hv;
    aggl[idx] = lv;
}

// ---------------- weight prep: fp32 -> bf16 hi/lo (row-major [K][N]) ----------------
__global__ void k_wprep(const float* __restrict__ W, __nv_bfloat16* __restrict__ wh,
                        __nv_bfloat16* __restrict__ wl, int n) {
    int i = blockIdx.x * 256 + threadIdx.x;
    if (i < n) {
        float f = W[i];
        __nv_bfloat16 h = __float2bfloat16(f);
        wh[i] = h;
        wl[i] = __float2bfloat16(f - __bfloat162float(h));
    }
}

// ---------------- mma.sync GEMM: C[M,BN] = A[M,32*KITER] @ W, bf16 hi/lo split ----------------
// A (bf16) layout: A[((k>>7)*NP + row)*128 + (k&127)]  (relation-chunked concat)
// B (bf16) row-major [K][BN]. 512 threads, BM=128, warp grid 4x4.
template <int BN, int KITER, int NREL, bool RELU, bool WB16>
__global__ __launch_bounds__(512) void k_mgemm(const __nv_bfloat16* __restrict__ Ah,
                                               const __nv_bfloat16* __restrict__ Al,
                                               const __nv_bfloat16* __restrict__ Bh,
                                               const __nv_bfloat16* __restrict__ Bl,
                                               const float* __restrict__ bias,
                                               float* __restrict__ C,
                                               uint32_t* __restrict__ Oh,
                                               uint32_t* __restrict__ Ol, int M) {
    constexpr int APITCH = 40;                 // bf16 units (80B rows: conflict-free ldsm)
    constexpr int BPITCH = BN + 8;             // bf16 units
    constexpr int ASZ = 128 * APITCH * 2;      // bytes per image (hi or lo)
    constexpr int BSZ = 32 * BPITCH * 2;
    constexpr int STG = 2 * ASZ + 2 * BSZ;
    constexpr int WN = BN / 4;                 // cols per warp
    constexpr int NT = WN / 8;                 // n-tiles per warp
    constexpr int NSEG = BN / 8;               // 16B segs per B row

    extern __shared__ char smem[];
    uint32_t sb = smem_u32(smem);
    const int tid = threadIdx.x;
    const int wid = tid >> 5, lane = tid & 31;
    const int warp_row = wid >> 2, warp_col = wid & 3;
    const int blockRow = blockIdx.x * 128;

    // chunk loader
    auto load_chunk = [&](int it, int s) {
        uint32_t stg = sb + s * STG;
        int kg = it * 32;
        int rel = kg >> 7, kloc = kg & 127;
        int arow = tid >> 2, aseg = tid & 3;
        size_t abase = ((size_t)rel * NP + blockRow + arow) * 128 + kloc + aseg * 8;
        uint32_t ad = stg + (arow * APITCH + aseg * 8) * 2;
        cpasync16(ad,       Ah + abase);
        cpasync16(ad + ASZ, Al + abase);
        if (tid < 32 * NSEG) {
            int brow = tid / NSEG, bseg = tid % NSEG;
            size_t bbase = (size_t)(kg + brow) * BN + bseg * 8;
            uint32_t bd = stg + 2 * ASZ + (brow * BPITCH + bseg * 8) * 2;
            cpasync16(bd,       Bh + bbase);
            cpasync16(bd + BSZ, Bl + bbase);
        }
    };

    float acc[2][NT][4];
    #pragma unroll
    for (int mt = 0; mt < 2; mt++)
        #pragma unroll
        for (int nt = 0; nt < NT; nt++)
            #pragma unroll
            for (int j = 0; j < 4; j++) acc[mt][nt][j] = 0.f;

    load_chunk(0, 0);
    cp_commit();

    #pragma unroll 1
    for (int it = 0; it < KITER; it++) {
        if (it + 1 < KITER) {
            load_chunk(it + 1, (it + 1) & 1);
            cp_commit();
            cp_wait<1>();
        } else {
            cp_wait<0>();
        }
        __syncthreads();
        uint32_t sA  = sb + (it & 1) * STG;
        uint32_t sB  = sA + 2 * ASZ;
        #pragma unroll
        for (int ks = 0; ks < 2; ks++) {
            uint32_t ah[2][4], al_[2][4];
            #pragma unroll
            for (int mt = 0; mt < 2; mt++) {
                uint32_t ad = sA + ((warp_row * 32 + mt * 16 + (lane & 15)) * APITCH +
                                    ks * 16 + (lane >> 4) * 8) * 2;
                ldsm_x4(ah[mt], ad);
                ldsm_x4(al_[mt], ad + ASZ);
            }
            uint32_t bh[NT / 2][4], bl[NT / 2][4];
            #pragma unroll
            for (int p = 0; p < NT / 2; p++) {
                uint32_t bd = sB + ((ks * 16 + (lane & 15)) * BPITCH +
                                    warp_col * WN + p * 16 + (lane >> 4) * 8) * 2;
                ldsm_x4t(bh[p], bd);
                ldsm_x4t(bl[p], bd + BSZ);
            }
            #pragma unroll
            for (int mt = 0; mt < 2; mt++)
                #pragma unroll
                for (int nt = 0; nt < NT; nt++) {
                    const uint32_t* bhp = &bh[nt >> 1][(nt & 1) * 2];
                    const uint32_t* blp = &bl[nt >> 1][(nt & 1) * 2];
                    mma16816(acc[mt][nt], ah[mt], bhp);
                    mma16816(acc[mt][nt], ah[mt], blp);
                    mma16816(acc[mt][nt], al_[mt], bhp);
                }
        }
        __syncthreads();
    }

    // epilogue: bias (+mean fold) + leaky-relu + store
    const int lane4 = lane >> 2, lane2 = lane & 3;
    #pragma unroll
    for (int mt = 0; mt < 2; mt++) {
        int row0 = blockRow + warp_row * 32 + mt * 16 + lane4;
        #pragma unroll
        for (int nt = 0; nt < NT; nt++) {
            int col = warp_col * WN + nt * 8 + lane2 * 2;
            float b0, b1;
            if (NREL == 3) {
                b0 = (__ldg(&bias[col])     + __ldg(&bias[FD + col])     + __ldg(&bias[2 * FD + col]))     * (1.f / 3.f);
                b1 = (__ldg(&bias[col + 1]) + __ldg(&bias[FD + col + 1]) + __ldg(&bias[2 * FD + col + 1])) * (1.f / 3.f);
            } else {
                b0 = __ldg(&bias[col]);
                b1 = __ldg(&bias[col + 1]);
            }
            #pragma unroll
            for (int h = 0; h < 2; h++) {
                int row = row0 + h * 8;
                if (row < M) {
                    float v0 = acc[mt][nt][h * 2 + 0] + b0;
                    float v1 = acc[mt][nt][h * 2 + 1] + b1;
                    if (RELU) {
                        v0 = (v0 > 0.f) ? v0 : 0.01f * v0;
                        v1 = (v1 > 0.f) ? v1 : 0.01f * v1;
                    }
                    float2 v = {v0, v1};
                    *reinterpret_cast<float2*>(&C[(size_t)row * BN + col]) = v;
                    if (WB16) {
                        __nv_bfloat162 hh(__float2bfloat16(v0), __float2bfloat16(v1));
                        __nv_bfloat162 ll(__float2bfloat16(v0 - __bfloat162float(hh.x)),
                                          __float2bfloat16(v1 - __bfloat162float(hh.y)));
                        Oh[(size_t)row * 64 + (col >> 1)] = *reinterpret_cast<uint32_t*>(&hh);
                        Ol[(size_t)row * 64 + (col >> 1)] = *reinterpret_cast<uint32_t*>(&ll);
                    }
                }
            }
        }
    }
}

// ---------------- launch ----------------
extern "C" void kernel_launch(void* const* d_in, const int* in_sizes, int n_in,
                              void* d_out, int out_size) {
    const float* x    = (const float*)d_in[0];
    const int*   esrc = (const int*)  d_in[1];
    const int*   edst = (const int*)  d_in[2];
    const float* W0   = (const float*)d_in[3];
    const float* b0   = (const float*)d_in[4];
    const float* Wl   = (const float*)d_in[5];
    const float* bl   = (const float*)d_in[6];
    const float* Wout = (const float*)d_in[7];
    const float* bout = (const float*)d_in[8];
    float* out = (float*)d_out;

    void *p_od, *p_id, *p_fl, *p_h0, *p_h1, *p_aggh, *p_aggl, *p_hbh, *p_hbl, *p_wh, *p_wl;
    cudaGetSymbolAddress(&p_od, g_outdeg);
    cudaGetSymbolAddress(&p_id, g_indeg);
    cudaGetSymbolAddress(&p_fl, g_fill);
    cudaGetSymbolAddress(&p_h0, g_h0);
    cudaGetSymbolAddress(&p_h1, g_h1);
    cudaGetSymbolAddress(&p_aggh, g_aggh);
    cudaGetSymbolAddress(&p_aggl, g_aggl);
    cudaGetSymbolAddress(&p_hbh, g_hbh);
    cudaGetSymbolAddress(&p_hbl, g_hbl);
    cudaGetSymbolAddress(&p_wh, g_wh);
    cudaGetSymbolAddress(&p_wl, g_wl);

    // dynamic smem: BN=128 -> 2*(2*10240 + 2*8704) = 75776 ; BN=64 -> 2*(2*10240 + 2*4608) = 59392
    cudaFuncSetAttribute(k_mgemm<128, 12, 3, true,  false>, cudaFuncAttributeMaxDynamicSharedMemorySize, 75776);
    cudaFuncSetAttribute(k_mgemm<128, 12, 3, false, true >, cudaFuncAttributeMaxDynamicSharedMemorySize, 75776);
    cudaFuncSetAttribute(k_mgemm<64,  4,  1, false, false>, cudaFuncAttributeMaxDynamicSharedMemorySize, 59392);

    cudaMemsetAsync(p_od, 0, sizeof(int) * RR * NN);
    cudaMemsetAsync(p_id, 0, sizeof(int) * RR * NN);
    cudaMemsetAsync(p_fl, 0, sizeof(int) * RR * NN);

    dim3 ge((EE + 255) / 256, RR);
    k_degree<<<ge, 256>>>(esrc, edst);
    k_scan<<<RR, 1024>>>();
    k_fill<<<ge, 256>>>(esrc, edst);

    float4* hbuf[2] = { (float4*)p_h0, (float4*)p_h1 };
    uint2* aggh = (uint2*)p_aggh;
    uint2* aggl = (uint2*)p_aggl;
    const __nv_bfloat16* wh = (const __nv_bfloat16*)p_wh;
    const __nv_bfloat16* wl = (const __nv_bfloat16*)p_wl;

    dim3 gs((NN + 7) / 8, RR);
    const int GB = (NN + 127) / 128;   // 391

    const float4* cur = (const float4*)x;
    for (int l = 0; l < 5; l++) {
        k_spmm<<<gs, 256>>>(cur, aggh, aggl);
        const float* W = (l == 0) ? W0 : (Wl + (size_t)(l - 1) * RR * FD * FD);
        const float* b = (l == 0) ? b0 : (bl + (size_t)(l - 1) * RR * FD);
        k_wprep<<<(RR * FD * FD + 255) / 256, 256>>>(W, (__nv_bfloat16*)p_wh, (__nv_bfloat16*)p_wl, RR * FD * FD);
        float* hout = (float*)hbuf[l & 1];
        if (l < 4)
            k_mgemm<128, 12, 3, true, false><<<GB, 512, 75776>>>(
                (const __nv_bfloat16*)aggh, (const __nv_bfloat16*)aggl, wh, wl, b,
                hout, nullptr, nullptr, NN);
        else
            k_mgemm<128, 12, 3, false, true><<<GB, 512, 75776>>>(
                (const __nv_bfloat16*)aggh, (const __nv_bfloat16*)aggl, wh, wl, b,
                hout, (uint32_t*)p_hbh, (uint32_t*)p_hbl, NN);
        cur = (const float4*)hout;
    }

    k_wprep<<<(FD * OUTD + 255) / 256, 256>>>(Wout, (__nv_bfloat16*)p_wh, (__nv_bfloat16*)p_wl, FD * OUTD);
    k_mgemm<64, 4, 1, false, false><<<GB, 512, 59392>>>(
        (const __nv_bfloat16*)p_hbh, (const __nv_bfloat16*)p_hbl, wh, wl, bout,
        out, nullptr, nullptr, NN);
}

// round 6
// speedup vs baseline: 2.1138x; 1.0013x over previous
#include <cuda_runtime.h>
#include <cuda_bf16.h>
#include <cstdint>

#define NN   50000
#define NP   50128           // padded rows (OOB-safe cp.async for last block)
#define FD   128
#define RR   3
#define EE   800000
#define OUTD 64
#define NNFD ((size_t)NN * FD)
#define WLAYER (RR * FD * FD)          // 49152 per hidden layer
#define WTOT   (5 * WLAYER + FD * OUTD)

// ---------------- static device scratch ----------------
__device__ float4 g_h0[NNFD / 4];
__device__ float4 g_h1[NNFD / 4];
__device__ uint2  g_aggh[(size_t)RR * NP * 32];   // bf16 hi image of agg [r][row][128]
__device__ uint2  g_aggl[(size_t)RR * NP * 32];   // bf16 lo image
__device__ uint32_t g_hbh[(size_t)NP * 64];       // bf16 hi of layer-4 output [row][128]
__device__ uint32_t g_hbl[(size_t)NP * 64];
__device__ __nv_bfloat16 g_wh[WTOT];              // weight hi, all layers ([K][N] row-major each)
__device__ __nv_bfloat16 g_wl[WTOT];
__device__ int    g_rowptr[RR * (NN + 1)];
__device__ int    g_cnt[3 * RR * NN];             // [outdeg | indeg | fill] contiguous
__device__ int    g_srcoff[(size_t)RR * EE];      // src*32 (float4 units), CSR-ordered by dst
__device__ float  g_coef[(size_t)RR * EE];        // norm coef (incl. 1/3 mean fold)

#define ODEG(r, n) g_cnt[(r) * NN + (n)]
#define IDEG(r, n) g_cnt[RR * NN + (r) * NN + (n)]
#define FILL(r, n) g_cnt[2 * RR * NN + (r) * NN + (n)]

// ---------------- ptx helpers (baseline PTX only) ----------------
__device__ __forceinline__ uint32_t smem_u32(const void* p) {
    uint32_t a;
    asm("{ .reg .u64 t; cvta.to.shared.u64 t, %1; cvt.u32.u64 %0, t; }" : "=r"(a) : "l"(p));
    return a;
}
__device__ __forceinline__ void cpasync16(uint32_t sdst, const void* gsrc) {
    asm volatile("cp.async.cg.shared.global [%0], [%1], 16;" :: "r"(sdst), "l"(gsrc) : "memory");
}
__device__ __forceinline__ void cp_commit() {
    asm volatile("cp.async.commit_group;" ::: "memory");
}
template <int N>
__device__ __forceinline__ void cp_wait() {
    asm volatile("cp.async.wait_group %0;" :: "n"(N) : "memory");
}
__device__ __forceinline__ void ldsm_x4(uint32_t* r, uint32_t addr) {
    asm volatile("ldmatrix.sync.aligned.m8n8.x4.shared.b16 {%0,%1,%2,%3}, [%4];"
                 : "=r"(r[0]), "=r"(r[1]), "=r"(r[2]), "=r"(r[3]) : "r"(addr));
}
__device__ __forceinline__ void ldsm_x4t(uint32_t* r, uint32_t addr) {
    asm volatile("ldmatrix.sync.aligned.m8n8.x4.trans.shared.b16 {%0,%1,%2,%3}, [%4];"
                 : "=r"(r[0]), "=r"(r[1]), "=r"(r[2]), "=r"(r[3]) : "r"(addr));
}
__device__ __forceinline__ void mma16816(float* d, const uint32_t* a, const uint32_t* b) {
    asm volatile("mma.sync.aligned.m16n8k16.row.col.f32.bf16.bf16.f32 "
                 "{%0,%1,%2,%3},{%4,%5,%6,%7},{%8,%9},{%0,%1,%2,%3};"
                 : "+f"(d[0]), "+f"(d[1]), "+f"(d[2]), "+f"(d[3])
                 : "r"(a[0]), "r"(a[1]), "r"(a[2]), "r"(a[3]), "r"(b[0]), "r"(b[1]));
}

// ---------------- degree histogram ----------------
__global__ void k_degree(const int* __restrict__ src, const int* __restrict__ dst) {
    int e = blockIdx.x * blockDim.x + threadIdx.x;
    int r = blockIdx.y;
    if (e < EE) {
        atomicAdd(&ODEG(r, src[(size_t)r * EE + e]), 1);
        atomicAdd(&IDEG(r, dst[(size_t)r * EE + e]), 1);
    }
}

// ---------------- exclusive scan of in-degree -> rowptr (chunk-per-thread, 3 syncs) ----------------
__global__ void k_scan() {
    constexpr int CH = (NN + 1023) / 1024;    // 49
    int r = blockIdx.x, t = threadIdx.x, lane = t & 31, wid = t >> 5;
    __shared__ int wsum[32];
    int base = t * CH;
    int s = 0;
    #pragma unroll 1
    for (int i = 0; i < CH; i++) {
        int idx = base + i;
        if (idx < NN) s += IDEG(r, idx);
    }
    // block-wide exclusive scan of per-thread sums
    int incl = s;
    #pragma unroll
    for (int d = 1; d < 32; d <<= 1) {
        int u = __shfl_up_sync(0xffffffffu, incl, d);
        if (lane >= d) incl += u;
    }
    if (lane == 31) wsum[wid] = incl;
    __syncthreads();
    if (wid == 0) {
        int w = wsum[lane];
        int wi = w;
        #pragma unroll
        for (int d = 1; d < 32; d <<= 1) {
            int u = __shfl_up_sync(0xffffffffu, wi, d);
            if (lane >= d) wi += u;
        }
        wsum[lane] = wi - w;
    }
    __syncthreads();
    int pre = wsum[wid] + incl - s;           // exclusive prefix for this thread's chunk
    #pragma unroll 1
    for (int i = 0; i < CH; i++) {
        int idx = base + i;
        if (idx < NN) {
            g_rowptr[r * (NN + 1) + idx] = pre;
            pre += IDEG(r, idx);
        }
    }
    if (t == 1023) g_rowptr[r * (NN + 1) + NN] = pre;
}

// ---------------- counting-sort fill: CSR by dst + edge coefficient ----------------
__global__ void k_fill(const int* __restrict__ src, const int* __restrict__ dst) {
    int e = blockIdx.x * blockDim.x + threadIdx.x;
    int r = blockIdx.y;
    if (e < EE) {
        int s = src[(size_t)r * EE + e];
        int d = dst[(size_t)r * EE + e];
        int pos = g_rowptr[r * (NN + 1) + d] + atomicAdd(&FILL(r, d), 1);
        float no = rsqrtf(fmaxf((float)ODEG(r, s), 1.f));
        float ni = rsqrtf(fmaxf((float)IDEG(r, d), 1.f));
        g_srcoff[(size_t)r * EE + pos] = s * 32;      // float4 units
        g_coef  [(size_t)r * EE + pos] = no * ni * (1.f / 3.f);
    }
}

// ---------------- SpMM: warp-per-row float4 gathers (MLP=8); epilogue emits bf16 hi/lo ----------------
__global__ __launch_bounds__(256) void k_spmm(const float4* __restrict__ h4,
                                              uint2* __restrict__ aggh,
                                              uint2* __restrict__ aggl) {
    int r = blockIdx.y;
    int row = blockIdx.x * 8 + (threadIdx.x >> 5);
    int lane = threadIdx.x & 31;
    if (row >= NN) return;
    int beg = g_rowptr[r * (NN + 1) + row];
    int end = g_rowptr[r * (NN + 1) + row + 1];
    const int*   si = &g_srcoff[(size_t)r * EE];
    const float* cf = &g_coef  [(size_t)r * EE];
    float4 acc = {0.f, 0.f, 0.f, 0.f};
    int e = beg;
    for (; e + 8 <= end; e += 8) {
        int o[8]; float c[8]; float4 v[8];
        #pragma unroll
        for (int j = 0; j < 8; j++) o[j] = __ldg(&si[e + j]);
        #pragma unroll
        for (int j = 0; j < 8; j++) c[j] = __ldg(&cf[e + j]);
        #pragma unroll
        for (int j = 0; j < 8; j++) v[j] = __ldg(&h4[o[j] + lane]);
        #pragma unroll
        for (int j = 0; j < 8; j++) {
            acc.x += c[j] * v[j].x;
            acc.y += c[j] * v[j].y;
            acc.z += c[j] * v[j].z;
            acc.w += c[j] * v[j].w;
        }
    }
    if (e + 4 <= end) {
        int o[4]; float c[4]; float4 v[4];
        #pragma unroll
        for (int j = 0; j < 4; j++) o[j] = __ldg(&si[e + j]);
        #pragma unroll
        for (int j = 0; j < 4; j++) c[j] = __ldg(&cf[e + j]);
        #pragma unroll
        for (int j = 0; j < 4; j++) v[j] = __ldg(&h4[o[j] + lane]);
        #pragma unroll
        for (int j = 0; j < 4; j++) {
            acc.x += c[j] * v[j].x;
            acc.y += c[j] * v[j].y;
            acc.z += c[j] * v[j].z;
            acc.w += c[j] * v[j].w;
        }
        e += 4;
    }
    for (; e < end; e++) {
        float c = __ldg(&cf[e]);
        float4 v = __ldg(&h4[__ldg(&si[e]) + lane]);
        acc.x += c * v.x; acc.y += c * v.y; acc.z += c * v.z; acc.w += c * v.w;
    }
    // split into bf16 hi/lo and store
    __nv_bfloat162 h01(__float2bfloat16(acc.x), __float2bfloat16(acc.y));
    __nv_bfloat162 h23(__float2bfloat16(acc.z), __float2bfloat16(acc.w));
    __nv_bfloat162 l01(__float2bfloat16(acc.x - __bfloat162float(h01.x)),
                       __float2bfloat16(acc.y - __bfloat162float(h01.y)));
    __nv_bfloat162 l23(__float2bfloat16(acc.z - __bfloat162float(h23.x)),
                       __float2bfloat16(acc.w - __bfloat162float(h23.y)));
    size_t idx = ((size_t)r * NP + row) * 32 + lane;
    uint2 hv = { *reinterpret_cast<uint32_t*>(&h01), *reinterpret_cast<uint32_t*>(&h23) };
    uint2 lv = { *reinterpret_cast<uint32_t*>(&l01), *reinterpret_cast<uint32_t*>(&l23) };
    aggh[idx] = hv;
    aggl[idx] = lv;
}

// ---------------- weight prep: ALL layers fp32 -> bf16 hi/lo in one launch ----------------
__global__ void k_wprep_all(const float* __restrict__ W0, const float* __restrict__ Wl,
                            const float* __restrict__ Wout) {
    int i = blockIdx.x * 256 + threadIdx.x;
    if (i >= WTOT) return;
    float f;
    if (i < WLAYER)                f = W0[i];
    else if (i < 5 * WLAYER)       f = Wl[i - WLAYER];
    else                           f = Wout[i - 5 * WLAYER];
    __nv_bfloat16 h = __float2bfloat16(f);
    g_wh[i] = h;
    g_wl[i] = __float2bfloat16(f - __bfloat162float(h));
}

// ---------------- mma.sync GEMM: C[M,BN] = A[M,32*KITER] @ W, bf16 hi/lo split ----------------
// A (bf16) layout: A[((k>>7)*NP + row)*128 + (k&127)]  (relation-chunked concat)
// B (bf16) row-major [K][BN]. 512 threads, BM=128, warp grid 4x4.
template <int BN, int KITER, int NREL, bool RELU, bool WB16>
__global__ __launch_bounds__(512) void k_mgemm(const __nv_bfloat16* __restrict__ Ah,
                                               const __nv_bfloat16* __restrict__ Al,
                                               const __nv_bfloat16* __restrict__ Bh,
                                               const __nv_bfloat16* __restrict__ Bl,
                                               const float* __restrict__ bias,
                                               float* __restrict__ C,
                                               uint32_t* __restrict__ Oh,
                                               uint32_t* __restrict__ Ol, int M) {
    constexpr int APITCH = 40;                 // bf16 units (80B rows: conflict-free ldsm)
    constexpr int BPITCH = BN + 8;
    constexpr int ASZ = 128 * APITCH * 2;
    constexpr int BSZ = 32 * BPITCH * 2;
    constexpr int STG = 2 * ASZ + 2 * BSZ;
    constexpr int WN = BN / 4;
    constexpr int NT = WN / 8;
    constexpr int NSEG = BN / 8;

    extern __shared__ char smem[];
    uint32_t sb = smem_u32(smem);
    const int tid = threadIdx.x;
    const int wid = tid >> 5, lane = tid & 31;
    const int warp_row = wid >> 2, warp_col = wid & 3;
    const int blockRow = blockIdx.x * 128;

    auto load_chunk = [&](int it, int s) {
        uint32_t stg = sb + s * STG;
        int kg = it * 32;
        int rel = kg >> 7, kloc = kg & 127;
        int arow = tid >> 2, aseg = tid & 3;
        size_t abase = ((size_t)rel * NP + blockRow + arow) * 128 + kloc + aseg * 8;
        uint32_t ad = stg + (arow * APITCH + aseg * 8) * 2;
        cpasync16(ad,       Ah + abase);
        cpasync16(ad + ASZ, Al + abase);
        if (tid < 32 * NSEG) {
            int brow = tid / NSEG, bseg = tid % NSEG;
            size_t bbase = (size_t)(kg + brow) * BN + bseg * 8;
            uint32_t bd = stg + 2 * ASZ + (brow * BPITCH + bseg * 8) * 2;
            cpasync16(bd,       Bh + bbase);
            cpasync16(bd + BSZ, Bl + bbase);
        }
    };

    float acc[2][NT][4];
    #pragma unroll
    for (int mt = 0; mt < 2; mt++)
        #pragma unroll
        for (int nt = 0; nt < NT; nt++)
            #pragma unroll
            for (int j = 0; j < 4; j++) acc[mt][nt][j] = 0.f;

    load_chunk(0, 0);
    cp_commit();

    #pragma unroll 1
    for (int it = 0; it < KITER; it++) {
        if (it + 1 < KITER) {
            load_chunk(it + 1, (it + 1) & 1);
            cp_commit();
            cp_wait<1>();
        } else {
            cp_wait<0>();
        }
        __syncthreads();
        uint32_t sA  = sb + (it & 1) * STG;
        uint32_t sB  = sA + 2 * ASZ;
        #pragma unroll
        for (int ks = 0; ks < 2; ks++) {
            uint32_t ah[2][4], al_[2][4];
            #pragma unroll
            for (int mt = 0; mt < 2; mt++) {
                uint32_t ad = sA + ((warp_row * 32 + mt * 16 + (lane & 15)) * APITCH +
                                    ks * 16 + (lane >> 4) * 8) * 2;
                ldsm_x4(ah[mt], ad);
                ldsm_x4(al_[mt], ad + ASZ);
            }
            uint32_t bh[NT / 2][4], bl[NT / 2][4];
            #pragma unroll
            for (int p = 0; p < NT / 2; p++) {
                uint32_t bd = sB + ((ks * 16 + (lane & 15)) * BPITCH +
                                    warp_col * WN + p * 16 + (lane >> 4) * 8) * 2;
                ldsm_x4t(bh[p], bd);
                ldsm_x4t(bl[p], bd + BSZ);
            }
            #pragma unroll
            for (int mt = 0; mt < 2; mt++)
                #pragma unroll
                for (int nt = 0; nt < NT; nt++) {
                    const uint32_t* bhp = &bh[nt >> 1][(nt & 1) * 2];
                    const uint32_t* blp = &bl[nt >> 1][(nt & 1) * 2];
                    mma16816(acc[mt][nt], ah[mt], bhp);
                    mma16816(acc[mt][nt], ah[mt], blp);
                    mma16816(acc[mt][nt], al_[mt], bhp);
                }
        }
        __syncthreads();
    }

    // epilogue: bias (+mean fold) + leaky-relu + store
    const int lane4 = lane >> 2, lane2 = lane & 3;
    #pragma unroll
    for (int mt = 0; mt < 2; mt++) {
        int row0 = blockRow + warp_row * 32 + mt * 16 + lane4;
        #pragma unroll
        for (int nt = 0; nt < NT; nt++) {
            int col = warp_col * WN + nt * 8 + lane2 * 2;
            float b0, b1;
            if (NREL == 3) {
                b0 = (__ldg(&bias[col])     + __ldg(&bias[FD + col])     + __ldg(&bias[2 * FD + col]))     * (1.f / 3.f);
                b1 = (__ldg(&bias[col + 1]) + __ldg(&bias[FD + col + 1]) + __ldg(&bias[2 * FD + col + 1])) * (1.f / 3.f);
            } else {
                b0 = __ldg(&bias[col]);
                b1 = __ldg(&bias[col + 1]);
            }
            #pragma unroll
            for (int h = 0; h < 2; h++) {
                int row = row0 + h * 8;
                if (row < M) {
                    float v0 = acc[mt][nt][h * 2 + 0] + b0;
                    float v1 = acc[mt][nt][h * 2 + 1] + b1;
                    if (RELU) {
                        v0 = (v0 > 0.f) ? v0 : 0.01f * v0;
                        v1 = (v1 > 0.f) ? v1 : 0.01f * v1;
                    }
                    float2 v = {v0, v1};
                    *reinterpret_cast<float2*>(&C[(size_t)row * BN + col]) = v;
                    if (WB16) {
                        __nv_bfloat162 hh(__float2bfloat16(v0), __float2bfloat16(v1));
                        __nv_bfloat162 ll(__float2bfloat16(v0 - __bfloat162float(hh.x)),
                                          __float2bfloat16(v1 - __bfloat162float(hh.y)));
                        Oh[(size_t)row * 64 + (col >> 1)] = *reinterpret_cast<uint32_t*>(&hh);
                        Ol[(size_t)row * 64 + (col >> 1)] = *reinterpret_cast<uint32_t*>(&ll);
                    }
                }
            }
        }
    }
}

// ---------------- launch ----------------
extern "C" void kernel_launch(void* const* d_in, const int* in_sizes, int n_in,
                              void* d_out, int out_size) {
    const float* x    = (const float*)d_in[0];
    const int*   esrc = (const int*)  d_in[1];
    const int*   edst = (const int*)  d_in[2];
    const float* W0   = (const float*)d_in[3];
    const float* b0   = (const float*)d_in[4];
    const float* Wl   = (const float*)d_in[5];
    const float* bl   = (const float*)d_in[6];
    const float* Wout = (const float*)d_in[7];
    const float* bout = (const float*)d_in[8];
    float* out = (float*)d_out;

    void *p_cnt, *p_h0, *p_h1, *p_aggh, *p_aggl, *p_hbh, *p_hbl, *p_wh, *p_wl;
    cudaGetSymbolAddress(&p_cnt, g_cnt);
    cudaGetSymbolAddress(&p_h0, g_h0);
    cudaGetSymbolAddress(&p_h1, g_h1);
    cudaGetSymbolAddress(&p_aggh, g_aggh);
    cudaGetSymbolAddress(&p_aggl, g_aggl);
    cudaGetSymbolAddress(&p_hbh, g_hbh);
    cudaGetSymbolAddress(&p_hbl, g_hbl);
    cudaGetSymbolAddress(&p_wh, g_wh);
    cudaGetSymbolAddress(&p_wl, g_wl);

    cudaFuncSetAttribute(k_mgemm<128, 12, 3, true,  false>, cudaFuncAttributeMaxDynamicSharedMemorySize, 75776);
    cudaFuncSetAttribute(k_mgemm<128, 12, 3, false, true >, cudaFuncAttributeMaxDynamicSharedMemorySize, 75776);
    cudaFuncSetAttribute(k_mgemm<64,  4,  1, false, false>, cudaFuncAttributeMaxDynamicSharedMemorySize, 59392);

    cudaMemsetAsync(p_cnt, 0, sizeof(int) * 3 * RR * NN);
    k_wprep_all<<<(WTOT + 255) / 256, 256>>>(W0, Wl, Wout);

    dim3 ge((EE + 255) / 256, RR);
    k_degree<<<ge, 256>>>(esrc, edst);
    k_scan<<<RR, 1024>>>();
    k_fill<<<ge, 256>>>(esrc, edst);

    float4* hbuf[2] = { (float4*)p_h0, (float4*)p_h1 };
    uint2* aggh = (uint2*)p_aggh;
    uint2* aggl = (uint2*)p_aggl;
    const __nv_bfloat16* wh = (const __nv_bfloat16*)p_wh;
    const __nv_bfloat16* wl = (const __nv_bfloat16*)p_wl;

    dim3 gs((NN + 7) / 8, RR);
    const int GB = (NN + 127) / 128;   // 391

    const float4* cur = (const float4*)x;
    for (int l = 0; l < 5; l++) {
        k_spmm<<<gs, 256>>>(cur, aggh, aggl);
        const float* b = (l == 0) ? b0 : (bl + (size_t)(l - 1) * RR * FD);
        const __nv_bfloat16* lwh = wh + (size_t)l * WLAYER;
        const __nv_bfloat16* lwl = wl + (size_t)l * WLAYER;
        float* hout = (float*)hbuf[l & 1];
        if (l < 4)
            k_mgemm<128, 12, 3, true, false><<<GB, 512, 75776>>>(
                (const __nv_bfloat16*)aggh, (const __nv_bfloat16*)aggl, lwh, lwl, b,
                hout, nullptr, nullptr, NN);
        else
            k_mgemm<128, 12, 3, false, true><<<GB, 512, 75776>>>(
                (const __nv_bfloat16*)aggh, (const __nv_bfloat16*)aggl, lwh, lwl, b,
                hout, (uint32_t*)p_hbh, (uint32_t*)p_hbl, NN);
        cur = (const float4*)hout;
    }

    k_mgemm<64, 4, 1, false, false><<<GB, 512, 59392>>>(
        (const __nv_bfloat16*)p_hbh, (const __nv_bfloat16*)p_hbl,
        wh + 5 * WLAYER, wl + 5 * WLAYER, bout,
        out, nullptr, nullptr, NN);
}

// round 8
// speedup vs baseline: 2.2400x; 1.0597x over previous
#include <cuda_runtime.h>
#include <cuda_bf16.h>
#include <cstdint>

#define NN   50000
#define NP   50128           // padded rows (OOB-safe cp.async for last block)
#define FD   128
#define RR   3
#define EE   800000
#define OUTD 64
#define NNFD ((size_t)NN * FD)
#define WLAYER (RR * FD * FD)          // 49152 per hidden layer
#define WHID   (4 * WLAYER)            // hidden layers 0..3
#define WFUSE  (RR * FD * OUTD)        // fused layer-4 weight [384][64]
#define WTOT   (WHID + WFUSE)

// ---------------- static device scratch ----------------
__device__ float4 g_h0[NNFD / 4];
__device__ float4 g_h1[NNFD / 4];
__device__ uint2  g_aggh[(size_t)RR * NP * 32];   // bf16 hi image of agg [r][row][128]
__device__ uint2  g_aggl[(size_t)RR * NP * 32];   // bf16 lo image
__device__ __nv_bfloat16 g_wh[WTOT];              // weight hi ([K][N] row-major per layer)
__device__ __nv_bfloat16 g_wl[WTOT];
__device__ float  g_biasf[OUTD];                  // fused final bias
__device__ int    g_rowptr[RR * (NN + 1)];
__device__ int    g_cnt[3 * RR * NN];             // [outdeg | indeg | fill] contiguous
__device__ int2   g_edge[(size_t)RR * EE];        // {src*32 (float4 units), coef bits}, CSR by dst

#define ODEG(r, n) g_cnt[(r) * NN + (n)]
#define IDEG(r, n) g_cnt[RR * NN + (r) * NN + (n)]
#define FILL(r, n) g_cnt[2 * RR * NN + (r) * NN + (n)]

// ---------------- ptx helpers (baseline PTX only) ----------------
__device__ __forceinline__ uint32_t smem_u32(const void* p) {
    uint32_t a;
    asm("{ .reg .u64 t; cvta.to.shared.u64 t, %1; cvt.u32.u64 %0, t; }" : "=r"(a) : "l"(p));
    return a;
}
__device__ __forceinline__ void cpasync16(uint32_t sdst, const void* gsrc) {
    asm volatile("cp.async.cg.shared.global [%0], [%1], 16;" :: "r"(sdst), "l"(gsrc) : "memory");
}
__device__ __forceinline__ void cp_commit() {
    asm volatile("cp.async.commit_group;" ::: "memory");
}
template <int N>
__device__ __forceinline__ void cp_wait() {
    asm volatile("cp.async.wait_group %0;" :: "n"(N) : "memory");
}
__device__ __forceinline__ void ldsm_x4(uint32_t* r, uint32_t addr) {
    asm volatile("ldmatrix.sync.aligned.m8n8.x4.shared.b16 {%0,%1,%2,%3}, [%4];"
                 : "=r"(r[0]), "=r"(r[1]), "=r"(r[2]), "=r"(r[3]) : "r"(addr));
}
__device__ __forceinline__ void ldsm_x4t(uint32_t* r, uint32_t addr) {
    asm volatile("ldmatrix.sync.aligned.m8n8.x4.trans.shared.b16 {%0,%1,%2,%3}, [%4];"
                 : "=r"(r[0]), "=r"(r[1]), "=r"(r[2]), "=r"(r[3]) : "r"(addr));
}
__device__ __forceinline__ void mma16816(float* d, const uint32_t* a, const uint32_t* b) {
    asm volatile("mma.sync.aligned.m16n8k16.row.col.f32.bf16.bf16.f32 "
                 "{%0,%1,%2,%3},{%4,%5,%6,%7},{%8,%9},{%0,%1,%2,%3};"
                 : "+f"(d[0]), "+f"(d[1]), "+f"(d[2]), "+f"(d[3])
                 : "r"(a[0]), "r"(a[1]), "r"(a[2]), "r"(a[3]), "r"(b[0]), "r"(b[1]));
}

// ---------------- degree histogram (4 edges / thread, int4 loads) ----------------
__global__ void k_degree(const int4* __restrict__ src4, const int4* __restrict__ dst4) {
    int i = blockIdx.x * blockDim.x + threadIdx.x;
    int r = blockIdx.y;
    if (i < EE / 4) {
        int4 s = __ldg(&src4[(size_t)r * (EE / 4) + i]);
        int4 d = __ldg(&dst4[(size_t)r * (EE / 4) + i]);
        atomicAdd(&ODEG(r, s.x), 1); atomicAdd(&ODEG(r, s.y), 1);
        atomicAdd(&ODEG(r, s.z), 1); atomicAdd(&ODEG(r, s.w), 1);
        atomicAdd(&IDEG(r, d.x), 1); atomicAdd(&IDEG(r, d.y), 1);
        atomicAdd(&IDEG(r, d.z), 1); atomicAdd(&IDEG(r, d.w), 1);
    }
}

// ---------------- exclusive scan of in-degree -> rowptr (chunk-per-thread) ----------------
__global__ void k_scan() {
    constexpr int CH = (NN + 1023) / 1024;    // 49
    int r = blockIdx.x, t = threadIdx.x, lane = t & 31, wid = t >> 5;
    __shared__ int wsum[32];
    int base = t * CH;
    int s = 0;
    #pragma unroll 1
    for (int i = 0; i < CH; i++) {
        int idx = base + i;
        if (idx < NN) s += IDEG(r, idx);
    }
    int incl = s;
    #pragma unroll
    for (int d = 1; d < 32; d <<= 1) {
        int u = __shfl_up_sync(0xffffffffu, incl, d);
        if (lane >= d) incl += u;
    }
    if (lane == 31) wsum[wid] = incl;
    __syncthreads();
    if (wid == 0) {
        int w = wsum[lane];
        int wi = w;
        #pragma unroll
        for (int d = 1; d < 32; d <<= 1) {
            int u = __shfl_up_sync(0xffffffffu, wi, d);
            if (lane >= d) wi += u;
        }
        wsum[lane] = wi - w;
    }
    __syncthreads();
    int pre = wsum[wid] + incl - s;
    #pragma unroll 1
    for (int i = 0; i < CH; i++) {
        int idx = base + i;
        if (idx < NN) {
            g_rowptr[r * (NN + 1) + idx] = pre;
            pre += IDEG(r, idx);
        }
    }
    if (t == 1023) g_rowptr[r * (NN + 1) + NN] = pre;
}

// ---------------- counting-sort fill: CSR by dst + edge coefficient (single int2 store) ----------------
__global__ void k_fill(const int* __restrict__ src, const int* __restrict__ dst) {
    int e = blockIdx.x * blockDim.x + threadIdx.x;
    int r = blockIdx.y;
    if (e < EE) {
        int s = src[(size_t)r * EE + e];
        int d = dst[(size_t)r * EE + e];
        int pos = g_rowptr[r * (NN + 1) + d] + atomicAdd(&FILL(r, d), 1);
        float no = rsqrtf(fmaxf((float)ODEG(r, s), 1.f));
        float ni = rsqrtf(fmaxf((float)IDEG(r, d), 1.f));
        int2 ev = { s * 32, __float_as_int(no * ni * (1.f / 3.f)) };
        g_edge[(size_t)r * EE + pos] = ev;
    }
}

// ---------------- SpMM: warp-per-row float4 gathers; epilogue emits bf16 hi/lo ----------------
__global__ __launch_bounds__(256) void k_spmm(const float4* __restrict__ h4,
                                              uint2* __restrict__ aggh,
                                              uint2* __restrict__ aggl) {
    int r = blockIdx.y;
    int row = blockIdx.x * 8 + (threadIdx.x >> 5);
    int lane = threadIdx.x & 31;
    if (row >= NN) return;
    int beg = g_rowptr[r * (NN + 1) + row];
    int end = g_rowptr[r * (NN + 1) + row + 1];
    const int2* ed = &g_edge[(size_t)r * EE];
    float4 acc = {0.f, 0.f, 0.f, 0.f};
    int e = beg;
    for (; e + 8 <= end; e += 8) {
        int2 ev[8]; float4 v[8];
        #pragma unroll
        for (int j = 0; j < 8; j++) ev[j] = __ldg(&ed[e + j]);
        #pragma unroll
        for (int j = 0; j < 8; j++) v[j] = __ldg(&h4[ev[j].x + lane]);
        #pragma unroll
        for (int j = 0; j < 8; j++) {
            float c = __int_as_float(ev[j].y);
            acc.x += c * v[j].x;
            acc.y += c * v[j].y;
            acc.z += c * v[j].z;
            acc.w += c * v[j].w;
        }
    }
    if (e + 4 <= end) {
        int2 ev[4]; float4 v[4];
        #pragma unroll
        for (int j = 0; j < 4; j++) ev[j] = __ldg(&ed[e + j]);
        #pragma unroll
        for (int j = 0; j < 4; j++) v[j] = __ldg(&h4[ev[j].x + lane]);
        #pragma unroll
        for (int j = 0; j < 4; j++) {
            float c = __int_as_float(ev[j].y);
            acc.x += c * v[j].x;
            acc.y += c * v[j].y;
            acc.z += c * v[j].z;
            acc.w += c * v[j].w;
        }
        e += 4;
    }
    for (; e < end; e++) {
        int2 ev = __ldg(&ed[e]);
        float c = __int_as_float(ev.y);
        float4 v = __ldg(&h4[ev.x + lane]);
        acc.x += c * v.x; acc.y += c * v.y; acc.z += c * v.z; acc.w += c * v.w;
    }
    __nv_bfloat162 h01(__float2bfloat16(acc.x), __float2bfloat16(acc.y));
    __nv_bfloat162 h23(__float2bfloat16(acc.z), __float2bfloat16(acc.w));
    __nv_bfloat162 l01(__float2bfloat16(acc.x - __bfloat162float(h01.x)),
                       __float2bfloat16(acc.y - __bfloat162float(h01.y)));
    __nv_bfloat162 l23(__float2bfloat16(acc.z - __bfloat162float(h23.x)),
                       __float2bfloat16(acc.w - __bfloat162float(h23.y)));
    size_t idx = ((size_t)r * NP + row) * 32 + lane;
    uint2 hv = { *reinterpret_cast<uint32_t*>(&h01), *reinterpret_cast<uint32_t*>(&h23) };
    uint2 lv = { *reinterpret_cast<uint32_t*>(&l01), *reinterpret_cast<uint32_t*>(&l23) };
    aggh[idx] = hv;
    aggl[idx] = lv;
}

// ---------------- weight prep: hidden layers 0..3 fp32 -> bf16 hi/lo ----------------
__global__ void k_wprep(const float* __restrict__ W0, const float* __restrict__ Wl) {
    int i = blockIdx.x * 256 + threadIdx.x;
    if (i >= WHID) return;
    float f = (i < WLAYER) ? W0[i] : Wl[i - WLAYER];
    __nv_bfloat16 h = __float2bfloat16(f);
    g_wh[i] = h;
    g_wl[i] = __float2bfloat16(f - __bfloat162float(h));
}

// ---------------- fused final layer: Wf = W4cat @ Wout, biasf = mean(b4) @ Wout + bout ----------------
__global__ void k_wfuse(const float* __restrict__ Wl, const float* __restrict__ Wout,
                        const float* __restrict__ bl, const float* __restrict__ bout) {
    int t = blockIdx.x * 256 + threadIdx.x;
    if (t < WFUSE) {
        int n = t & (OUTD - 1), m = t >> 6;
        const float* w4 = Wl + 3 * WLAYER + (size_t)m * FD;   // row m of [384][128]
        float s = 0.f;
        #pragma unroll 4
        for (int j = 0; j < FD; j++) s += w4[j] * __ldg(&Wout[(size_t)j * OUTD + n]);
        __nv_bfloat16 h = __float2bfloat16(s);
        g_wh[WHID + t] = h;
        g_wl[WHID + t] = __float2bfloat16(s - __bfloat162float(h));
    } else if (t < WFUSE + OUTD) {
        int n = t - WFUSE;
        const float* b4 = bl + 3 * RR * FD;
        float s = bout[n];
        for (int j = 0; j < FD; j++) {
            float bm = (b4[j] + b4[FD + j] + b4[2 * FD + j]) * (1.f / 3.f);
            s += bm * Wout[(size_t)j * OUTD + n];
        }
        g_biasf[n] = s;
    }
}

// ---------------- mma.sync GEMM: C[M,BN] = A[M,32*KITER] @ W, bf16 hi/lo split ----------------
// A (bf16) layout: A[((k>>7)*NP + row)*128 + (k&127)]  (relation-chunked concat)
// B (bf16) row-major [K][BN]. 512 threads, BM=128, warp grid 4x4.
template <int BN, int KITER, int NREL, bool RELU>
__global__ __launch_bounds__(512) void k_mgemm(const __nv_bfloat16* __restrict__ Ah,
                                               const __nv_bfloat16* __restrict__ Al,
                                               const __nv_bfloat16* __restrict__ Bh,
                                               const __nv_bfloat16* __restrict__ Bl,
                                               const float* __restrict__ bias,
                                               float* __restrict__ C, int M) {
    constexpr int APITCH = 40;                 // bf16 units (80B rows: conflict-free ldsm)
    constexpr int BPITCH = BN + 8;
    constexpr int ASZ = 128 * APITCH * 2;
    constexpr int BSZ = 32 * BPITCH * 2;
    constexpr int STG = 2 * ASZ + 2 * BSZ;
    constexpr int WN = BN / 4;
    constexpr int NT = WN / 8;
    constexpr int NSEG = BN / 8;

    extern __shared__ char smem[];
    uint32_t sb = smem_u32(smem);
    const int tid = threadIdx.x;
    const int wid = tid >> 5, lane = tid & 31;
    const int warp_row = wid >> 2, warp_col = wid & 3;
    const int blockRow = blockIdx.x * 128;

    auto load_chunk = [&](int it, int s) {
        uint32_t stg = sb + s * STG;
        int kg = it * 32;
        int rel = kg >> 7, kloc = kg & 127;
        int arow = tid >> 2, aseg = tid & 3;
        size_t abase = ((size_t)rel * NP + blockRow + arow) * 128 + kloc + aseg * 8;
        uint32_t ad = stg + (arow * APITCH + aseg * 8) * 2;
        cpasync16(ad,       Ah + abase);
        cpasync16(ad + ASZ, Al + abase);
        if (tid < 32 * NSEG) {
            int brow = tid / NSEG, bseg = tid % NSEG;
            size_t bbase = (size_t)(kg + brow) * BN + bseg * 8;
            uint32_t bd = stg + 2 * ASZ + (brow * BPITCH + bseg * 8) * 2;
            cpasync16(bd,       Bh + bbase);
            cpasync16(bd + BSZ, Bl + bbase);
        }
    };

    float acc[2][NT][4];
    #pragma unroll
    for (int mt = 0; mt < 2; mt++)
        #pragma unroll
        for (int nt = 0; nt < NT; nt++)
            #pragma unroll
            for (int j = 0; j < 4; j++) acc[mt][nt][j] = 0.f;

    load_chunk(0, 0);
    cp_commit();

    #pragma unroll 1
    for (int it = 0; it < KITER; it++) {
        if (it + 1 < KITER) {
            load_chunk(it + 1, (it + 1) & 1);
            cp_commit();
            cp_wait<1>();
        } else {
            cp_wait<0>();
        }
        __syncthreads();
        uint32_t sA  = sb + (it & 1) * STG;
        uint32_t sB  = sA + 2 * ASZ;
        #pragma unroll
        for (int ks = 0; ks < 2; ks++) {
            uint32_t ah[2][4], al_[2][4];
            #pragma unroll
            for (int mt = 0; mt < 2; mt++) {
                uint32_t ad = sA + ((warp_row * 32 + mt * 16 + (lane & 15)) * APITCH +
                                    ks * 16 + (lane >> 4) * 8) * 2;
                ldsm_x4(ah[mt], ad);
                ldsm_x4(al_[mt], ad + ASZ);
            }
            uint32_t bh[NT / 2][4], bl[NT / 2][4];
            #pragma unroll
            for (int p = 0; p < NT / 2; p++) {
                uint32_t bd = sB + ((ks * 16 + (lane & 15)) * BPITCH +
                                    warp_col * WN + p * 16 + (lane >> 4) * 8) * 2;
                ldsm_x4t(bh[p], bd);
                ldsm_x4t(bl[p], bd + BSZ);
            }
            #pragma unroll
            for (int mt = 0; mt < 2; mt++)
                #pragma unroll
                for (int nt = 0; nt < NT; nt++) {
                    const uint32_t* bhp = &bh[nt >> 1][(nt & 1) * 2];
                    const uint32_t* blp = &bl[nt >> 1][(nt & 1) * 2];
                    mma16816(acc[mt][nt], ah[mt], bhp);
                    mma16816(acc[mt][nt], ah[mt], blp);
                    mma16816(acc[mt][nt], al_[mt], bhp);
                }
        }
        __syncthreads();
    }

    // epilogue: bias (+mean fold) + leaky-relu + store
    const int lane4 = lane >> 2, lane2 = lane & 3;
    #pragma unroll
    for (int mt = 0; mt < 2; mt++) {
        int row0 = blockRow + warp_row * 32 + mt * 16 + lane4;
        #pragma unroll
        for (int nt = 0; nt < NT; nt++) {
            int col = warp_col * WN + nt * 8 + lane2 * 2;
            float b0, b1;
            if (NREL == 3) {
                b0 = (__ldg(&bias[col])     + __ldg(&bias[FD + col])     + __ldg(&bias[2 * FD + col]))     * (1.f / 3.f);
                b1 = (__ldg(&bias[col + 1]) + __ldg(&bias[FD + col + 1]) + __ldg(&bias[2 * FD + col + 1])) * (1.f / 3.f);
            } else {
                b0 = __ldg(&bias[col]);
                b1 = __ldg(&bias[col + 1]);
            }
            #pragma unroll
            for (int h = 0; h < 2; h++) {
                int row = row0 + h * 8;
                if (row < M) {
                    float v0 = acc[mt][nt][h * 2 + 0] + b0;
                    float v1 = acc[mt][nt][h * 2 + 1] + b1;
                    if (RELU) {
                        v0 = (v0 > 0.f) ? v0 : 0.01f * v0;
                        v1 = (v1 > 0.f) ? v1 : 0.01f * v1;
                    }
                    float2 v = {v0, v1};
                    *reinterpret_cast<float2*>(&C[(size_t)row * BN + col]) = v;
                }
            }
        }
    }
}

// ---------------- launch ----------------
extern "C" void kernel_launch(void* const* d_in, const int* in_sizes, int n_in,
                              void* d_out, int out_size) {
    const float* x    = (const float*)d_in[0];
    const int*   esrc = (const int*)  d_in[1];
    const int*   edst = (const int*)  d_in[2];
    const float* W0   = (const float*)d_in[3];
    const float* b0   = (const float*)d_in[4];
    const float* Wl   = (const float*)d_in[5];
    const float* bl   = (const float*)d_in[6];
    const float* Wout = (const float*)d_in[7];
    const float* bout = (const float*)d_in[8];
    float* out = (float*)d_out;

    void *p_cnt, *p_h0, *p_h1, *p_aggh, *p_aggl, *p_wh, *p_wl, *p_bf;
    cudaGetSymbolAddress(&p_cnt, g_cnt);
    cudaGetSymbolAddress(&p_h0, g_h0);
    cudaGetSymbolAddress(&p_h1, g_h1);
    cudaGetSymbolAddress(&p_aggh, g_aggh);
    cudaGetSymbolAddress(&p_aggl, g_aggl);
    cudaGetSymbolAddress(&p_wh, g_wh);
    cudaGetSymbolAddress(&p_wl, g_wl);
    cudaGetSymbolAddress(&p_bf, g_biasf);

    cudaFuncSetAttribute(k_mgemm<128, 12, 3, true >, cudaFuncAttributeMaxDynamicSharedMemorySize, 75776);
    cudaFuncSetAttribute(k_mgemm<64,  12, 1, false>, cudaFuncAttributeMaxDynamicSharedMemorySize, 59392);

    cudaMemsetAsync(p_cnt, 0, sizeof(int) * 3 * RR * NN);
    k_wprep<<<(WHID + 255) / 256, 256>>>(W0, Wl);
    k_wfuse<<<(WFUSE + OUTD + 255) / 256, 256>>>(Wl, Wout, bl, bout);

    dim3 gd((EE / 4 + 255) / 256, RR);
    k_degree<<<gd, 256>>>((const int4*)esrc, (const int4*)edst);
    k_scan<<<RR, 1024>>>();
    dim3 ge((EE + 255) / 256, RR);
    k_fill<<<ge, 256>>>(esrc, edst);

    float4* hbuf[2] = { (float4*)p_h0, (float4*)p_h1 };
    uint2* aggh = (uint2*)p_aggh;
    uint2* aggl = (uint2*)p_aggl;
    const __nv_bfloat16* wh = (const __nv_bfloat16*)p_wh;
    const __nv_bfloat16* wl = (const __nv_bfloat16*)p_wl;

    dim3 gs((NN + 7) / 8, RR);
    const int GB = (NN + 127) / 128;   // 391

    const float4* cur = (const float4*)x;
    for (int l = 0; l < 4; l++) {
        k_spmm<<<gs, 256>>>(cur, aggh, aggl);
        const float* b = (l == 0) ? b0 : (bl + (size_t)(l - 1) * RR * FD);
        float* hout = (float*)hbuf[l & 1];
        k_mgemm<128, 12, 3, true><<<GB, 512, 75776>>>(
            (const __nv_bfloat16*)aggh, (const __nv_bfloat16*)aggl,
            wh + (size_t)l * WLAYER, wl + (size_t)l * WLAYER, b,
            hout, NN);
        cur = (const float4*)hout;
    }

    // layer 4 fused with final Linear: out = agg @ (W4cat @ Wout) + biasf
    k_spmm<<<gs, 256>>>(cur, aggh, aggl);
    k_mgemm<64, 12, 1, false><<<GB, 512, 59392>>>(
        (const __nv_bfloat16*)aggh, (const __nv_bfloat16*)aggl,
        wh + WHID, wl + WHID, (const float*)p_bf,
        out, NN);
}

// round 13
// speedup vs baseline: 2.4076x; 1.0748x over previous
#include <cuda_runtime.h>
#include <cuda_bf16.h>
#include <cstdint>

#define NN   50000
#define NP   50128           // padded rows (OOB-safe cp.async for last block)
#define FD   128
#define RR   3
#define EE   800000
#define OUTD 64
#define NNFD ((size_t)NN * FD)
#define WLAYER (RR * FD * FD)          // 49152 per hidden layer
#define WHID   (4 * WLAYER)            // hidden layers 0..3
#define WFUSE  (RR * FD * OUTD)        // fused layer-4 weight [384][64]
#define WTOT   (WHID + WFUSE)
#define STILE  4096                    // scan tile (1024 thr x 4)
#define NB     ((NN + STILE - 1) / STILE)   // 13 tiles / relation
#define RPS    (NN + 4)                // rowptr row stride, multiple of 4 -> int4-aligned per relation

// ---------------- static device scratch ----------------
__device__ float4 g_h0[NNFD / 4];
__device__ float4 g_h1[NNFD / 4];
__device__ uint2  g_aggh[(size_t)RR * NP * 32];   // bf16 hi image of agg [r][row][128]
__device__ uint2  g_aggl[(size_t)RR * NP * 32];   // bf16 lo image
__device__ __nv_bfloat16 g_wh[WTOT];              // weight hi ([K][N] row-major per layer)
__device__ __nv_bfloat16 g_wl[WTOT];
__device__ float  g_biasf[OUTD];                  // fused final bias
__device__ int    g_rowptr[RR * RPS];             // per-relation rowptr (element NN = total)
__device__ int    g_wptr[RR * NN];                // working copy for fill's slot atomics
__device__ int    g_cnt[2 * RR * NN];             // [outdeg | indeg] contiguous
__device__ int    g_bsum[RR * NB];                // per-tile sums
__device__ int    g_bpre[RR * NB];                // per-tile exclusive prefixes
__device__ int2   g_edge[(size_t)RR * EE];        // {src*32 (float4 units), coef bits}, CSR by dst

#define ODEG(r, n) g_cnt[(r) * NN + (n)]
#define IDEG(r, n) g_cnt[RR * NN + (r) * NN + (n)]

// ---------------- ptx helpers (baseline PTX only) ----------------
__device__ __forceinline__ uint32_t smem_u32(const void* p) {
    uint32_t a;
    asm("{ .reg .u64 t; cvta.to.shared.u64 t, %1; cvt.u32.u64 %0, t; }" : "=r"(a) : "l"(p));
    return a;
}
__device__ __forceinline__ void cpasync16(uint32_t sdst, const void* gsrc) {
    asm volatile("cp.async.cg.shared.global [%0], [%1], 16;" :: "r"(sdst), "l"(gsrc) : "memory");
}
__device__ __forceinline__ void cp_commit() {
    asm volatile("cp.async.commit_group;" ::: "memory");
}
template <int N>
__device__ __forceinline__ void cp_wait() {
    asm volatile("cp.async.wait_group %0;" :: "n"(N) : "memory");
}
__device__ __forceinline__ void ldsm_x4(uint32_t* r, uint32_t addr) {
    asm volatile("ldmatrix.sync.aligned.m8n8.x4.shared.b16 {%0,%1,%2,%3}, [%4];"
                 : "=r"(r[0]), "=r"(r[1]), "=r"(r[2]), "=r"(r[3]) : "r"(addr));
}
__device__ __forceinline__ void ldsm_x4t(uint32_t* r, uint32_t addr) {
    asm volatile("ldmatrix.sync.aligned.m8n8.x4.trans.shared.b16 {%0,%1,%2,%3}, [%4];"
                 : "=r"(r[0]), "=r"(r[1]), "=r"(r[2]), "=r"(r[3]) : "r"(addr));
}
__device__ __forceinline__ void mma16816(float* d, const uint32_t* a, const uint32_t* b) {
    asm volatile("mma.sync.aligned.m16n8k16.row.col.f32.bf16.bf16.f32 "
                 "{%0,%1,%2,%3},{%4,%5,%6,%7},{%8,%9},{%0,%1,%2,%3};"
                 : "+f"(d[0]), "+f"(d[1]), "+f"(d[2]), "+f"(d[3])
                 : "r"(a[0]), "r"(a[1]), "r"(a[2]), "r"(a[3]), "r"(b[0]), "r"(b[1]));
}

// ---------------- degree histogram (4 edges / thread, int4 loads) ----------------
__global__ void k_degree(const int4* __restrict__ src4, const int4* __restrict__ dst4) {
    int i = blockIdx.x * blockDim.x + threadIdx.x;
    int r = blockIdx.y;
    if (i < EE / 4) {
        int4 s = __ldg(&src4[(size_t)r * (EE / 4) + i]);
        int4 d = __ldg(&dst4[(size_t)r * (EE / 4) + i]);
        atomicAdd(&ODEG(r, s.x), 1); atomicAdd(&ODEG(r, s.y), 1);
        atomicAdd(&ODEG(r, s.z), 1); atomicAdd(&ODEG(r, s.w), 1);
        atomicAdd(&IDEG(r, d.x), 1); atomicAdd(&IDEG(r, d.y), 1);
        atomicAdd(&IDEG(r, d.z), 1); atomicAdd(&IDEG(r, d.w), 1);
    }
}

// ---------------- scan phase 1: per-tile sums (coalesced int4) ----------------
__global__ __launch_bounds__(1024) void k_scan1() {
    int r = blockIdx.y, b = blockIdx.x, t = threadIdx.x;
    int lane = t & 31, wid = t >> 5;
    __shared__ int wsum[32];
    int base = b * STILE + t * 4;
    int s = 0;
    if (base + 3 < NN) {
        int4 v = *(const int4*)&IDEG(r, base);
        s = v.x + v.y + v.z + v.w;
    } else {
        #pragma unroll
        for (int j = 0; j < 4; j++)
            if (base + j < NN) s += IDEG(r, base + j);
    }
    #pragma unroll
    for (int d = 16; d > 0; d >>= 1) s += __shfl_down_sync(0xffffffffu, s, d);
    if (lane == 0) wsum[wid] = s;
    __syncthreads();
    if (wid == 0) {
        s = wsum[lane];
        #pragma unroll
        for (int d = 16; d > 0; d >>= 1) s += __shfl_down_sync(0xffffffffu, s, d);
        if (lane == 0) g_bsum[r * NB + b] = s;
    }
}

// ---------------- scan phase 2: scan the 13 tile sums per relation ----------------
__global__ void k_scan2() {
    int r = threadIdx.x;
    if (r < RR) {
        int pre = 0;
        #pragma unroll
        for (int i = 0; i < NB; i++) {
            int v = g_bsum[r * NB + i];
            g_bpre[r * NB + i] = pre;
            pre += v;
        }
        g_rowptr[r * RPS + NN] = pre;
    }
}

// ---------------- scan phase 3: block-local exclusive scan + tile offset ----------------
__global__ __launch_bounds__(1024) void k_scan3() {
    int r = blockIdx.y, b = blockIdx.x, t = threadIdx.x;
    int lane = t & 31, wid = t >> 5;
    __shared__ int wsum[32];
    int base = b * STILE + t * 4;
    int v0 = 0, v1 = 0, v2 = 0, v3 = 0;
    if (base + 3 < NN) {
        int4 v = *(const int4*)&IDEG(r, base);
        v0 = v.x; v1 = v.y; v2 = v.z; v3 = v.w;
    } else {
        if (base + 0 < NN) v0 = IDEG(r, base + 0);
        if (base + 1 < NN) v1 = IDEG(r, base + 1);
        if (base + 2 < NN) v2 = IDEG(r, base + 2);
        if (base + 3 < NN) v3 = IDEG(r, base + 3);
    }
    int ts = v0 + v1 + v2 + v3;
    int incl = ts;
    #pragma unroll
    for (int d = 1; d < 32; d <<= 1) {
        int u = __shfl_up_sync(0xffffffffu, incl, d);
        if (lane >= d) incl += u;
    }
    if (lane == 31) wsum[wid] = incl;
    __syncthreads();
    if (wid == 0) {
        int w = wsum[lane];
        int wi = w;
        #pragma unroll
        for (int d = 1; d < 32; d <<= 1) {
            int u = __shfl_up_sync(0xffffffffu, wi, d);
            if (lane >= d) wi += u;
        }
        wsum[lane] = wi - w;
    }
    __syncthreads();
    int pre = g_bpre[r * NB + b] + wsum[wid] + incl - ts;
    int p0 = pre, p1 = p0 + v0, p2 = p1 + v1, p3 = p2 + v2;
    if (base + 3 < NN) {
        int4 pv = {p0, p1, p2, p3};
        *(int4*)&g_rowptr[r * RPS + base] = pv;     // RPS % 4 == 0 -> 16B-aligned
        *(int4*)&g_wptr[r * NN + base] = pv;        // NN  % 4 == 0 -> 16B-aligned
    } else {
        int pp[4] = {p0, p1, p2, p3};
        #pragma unroll
        for (int j = 0; j < 4; j++)
            if (base + j < NN) {
                g_rowptr[r * RPS + base + j] = pp[j];
                g_wptr[r * NN + base + j] = pp[j];
            }
    }
}

// ---------------- counting-sort fill: direct slot atomic + single int2 store ----------------
__global__ void k_fill(const int* __restrict__ src, const int* __restrict__ dst) {
    int e = blockIdx.x * blockDim.x + threadIdx.x;
    int r = blockIdx.y;
    if (e < EE) {
        int s = src[(size_t)r * EE + e];
        int d = dst[(size_t)r * EE + e];
        int pos = atomicAdd(&g_wptr[r * NN + d], 1);
        float no = rsqrtf(fmaxf((float)ODEG(r, s), 1.f));
        float ni = rsqrtf(fmaxf((float)IDEG(r, d), 1.f));
        int2 ev = { s * 32, __float_as_int(no * ni * (1.f / 3.f)) };
        g_edge[(size_t)r * EE + pos] = ev;
    }
}

// ---------------- SpMM: warp-per-row float4 gathers; epilogue emits bf16 hi/lo ----------------
__global__ __launch_bounds__(256) void k_spmm(const float4* __restrict__ h4,
                                              uint2* __restrict__ aggh,
                                              uint2* __restrict__ aggl) {
    int r = blockIdx.y;
    int row = blockIdx.x * 8 + (threadIdx.x >> 5);
    int lane = threadIdx.x & 31;
    if (row >= NN) return;
    int beg = g_rowptr[r * RPS + row];
    int end = g_rowptr[r * RPS + row + 1];
    if (row == NN - 1) end = g_rowptr[r * RPS + NN];
    const int2* ed = &g_edge[(size_t)r * EE];
    float4 acc = {0.f, 0.f, 0.f, 0.f};
    int e = beg;
    for (; e + 8 <= end; e += 8) {
        int2 ev[8]; float4 v[8];
        #pragma unroll
        for (int j = 0; j < 8; j++) ev[j] = __ldg(&ed[e + j]);
        #pragma unroll
        for (int j = 0; j < 8; j++) v[j] = __ldg(&h4[ev[j].x + lane]);
        #pragma unroll
        for (int j = 0; j < 8; j++) {
            float c = __int_as_float(ev[j].y);
            acc.x += c * v[j].x;
            acc.y += c * v[j].y;
            acc.z += c * v[j].z;
            acc.w += c * v[j].w;
        }
    }
    if (e + 4 <= end) {
        int2 ev[4]; float4 v[4];
        #pragma unroll
        for (int j = 0; j < 4; j++) ev[j] = __ldg(&ed[e + j]);
        #pragma unroll
        for (int j = 0; j < 4; j++) v[j] = __ldg(&h4[ev[j].x + lane]);
        #pragma unroll
        for (int j = 0; j < 4; j++) {
            float c = __int_as_float(ev[j].y);
            acc.x += c * v[j].x;
            acc.y += c * v[j].y;
            acc.z += c * v[j].z;
            acc.w += c * v[j].w;
        }
        e += 4;
    }
    for (; e < end; e++) {
        int2 ev = __ldg(&ed[e]);
        float c = __int_as_float(ev.y);
        float4 v = __ldg(&h4[ev.x + lane]);
        acc.x += c * v.x; acc.y += c * v.y; acc.z += c * v.z; acc.w += c * v.w;
    }
    __nv_bfloat162 h01(__float2bfloat16(acc.x), __float2bfloat16(acc.y));
    __nv_bfloat162 h23(__float2bfloat16(acc.z), __float2bfloat16(acc.w));
    __nv_bfloat162 l01(__float2bfloat16(acc.x - __bfloat162float(h01.x)),
                       __float2bfloat16(acc.y - __bfloat162float(h01.y)));
    __nv_bfloat162 l23(__float2bfloat16(acc.z - __bfloat162float(h23.x)),
                       __float2bfloat16(acc.w - __bfloat162float(h23.y)));
    size_t idx = ((size_t)r * NP + row) * 32 + lane;
    uint2 hv = { *reinterpret_cast<uint32_t*>(&h01), *reinterpret_cast<uint32_t*>(&h23) };
    uint2 lv = { *reinterpret_cast<uint32_t*>(&l01), *reinterpret_cast<uint32_t*>(&l23) };
    aggh[idx] = hv;
    aggl[idx] = lv;
}

// ---------------- weight prep: hidden layers 0..3 fp32 -> bf16 hi/lo ----------------
__global__ void k_wprep(const float* __restrict__ W0, const float* __restrict__ Wl) {
    int i = blockIdx.x * 256 + threadIdx.x;
    if (i >= WHID) return;
    float f = (i < WLAYER) ? W0[i] : Wl[i - WLAYER];
    __nv_bfloat16 h = __float2bfloat16(f);
    g_wh[i] = h;
    g_wl[i] = __float2bfloat16(f - __bfloat162float(h));
}

// ---------------- fused final layer: Wf = W4cat @ Wout, biasf = mean(b4) @ Wout + bout ----------------
__global__ void k_wfuse(const float* __restrict__ Wl, const float* __restrict__ Wout,
                        const float* __restrict__ bl, const float* __restrict__ bout) {
    int t = blockIdx.x * 256 + threadIdx.x;
    if (t < WFUSE) {
        int n = t & (OUTD - 1), m = t >> 6;
        const float* w4 = Wl + 3 * WLAYER + (size_t)m * FD;   // row m of [384][128]
        float s = 0.f;
        #pragma unroll 4
        for (int j = 0; j < FD; j++) s += w4[j] * __ldg(&Wout[(size_t)j * OUTD + n]);
        __nv_bfloat16 h = __float2bfloat16(s);
        g_wh[WHID + t] = h;
        g_wl[WHID + t] = __float2bfloat16(s - __bfloat162float(h));
    } else if (t < WFUSE + OUTD) {
        int n = t - WFUSE;
        const float* b4 = bl + 3 * RR * FD;
        float s = bout[n];
        for (int j = 0; j < FD; j++) {
            float bm = (b4[j] + b4[FD + j] + b4[2 * FD + j]) * (1.f / 3.f);
            s += bm * Wout[(size_t)j * OUTD + n];
        }
        g_biasf[n] = s;
    }
}

// ---------------- mma.sync GEMM: C[M,BN] = A[M,32*KITER] @ W, bf16 hi/lo split ----------------
// A (bf16) layout: A[((k>>7)*NP + row)*128 + (k&127)]  (relation-chunked concat)
// B (bf16) row-major [K][BN]. 512 threads, BM=128, warp grid 4x4.
template <int BN, int KITER, int NREL, bool RELU>
__global__ __launch_bounds__(512) void k_mgemm(const __nv_bfloat16* __restrict__ Ah,
                                               const __nv_bfloat16* __restrict__ Al,
                                               const __nv_bfloat16* __restrict__ Bh,
                                               const __nv_bfloat16* __restrict__ Bl,
                                               const float* __restrict__ bias,
                                               float* __restrict__ C, int M) {
    constexpr int APITCH = 40;                 // bf16 units (80B rows: conflict-free ldsm)
    constexpr int BPITCH = BN + 8;
    constexpr int ASZ = 128 * APITCH * 2;
    constexpr int BSZ = 32 * BPITCH * 2;
    constexpr int STG = 2 * ASZ + 2 * BSZ;
    constexpr int WN = BN / 4;
    constexpr int NT = WN / 8;
    constexpr int NSEG = BN / 8;

    extern __shared__ char smem[];
    uint32_t sb = smem_u32(smem);
    const int tid = threadIdx.x;
    const int wid = tid >> 5, lane = tid & 31;
    const int warp_row = wid >> 2, warp_col = wid & 3;
    const int blockRow = blockIdx.x * 128;

    auto load_chunk = [&](int it, int s) {
        uint32_t stg = sb + s * STG;
        int kg = it * 32;
        int rel = kg >> 7, kloc = kg & 127;
        int arow = tid >> 2, aseg = tid & 3;
        size_t abase = ((size_t)rel * NP + blockRow + arow) * 128 + kloc + aseg * 8;
        uint32_t ad = stg + (arow * APITCH + aseg * 8) * 2;
        cpasync16(ad,       Ah + abase);
        cpasync16(ad + ASZ, Al + abase);
        if (tid < 32 * NSEG) {
            int brow = tid / NSEG, bseg = tid % NSEG;
            size_t bbase = (size_t)(kg + brow) * BN + bseg * 8;
            uint32_t bd = stg + 2 * ASZ + (brow * BPITCH + bseg * 8) * 2;
            cpasync16(bd,       Bh + bbase);
            cpasync16(bd + BSZ, Bl + bbase);
        }
    };

    float acc[2][NT][4];
    #pragma unroll
    for (int mt = 0; mt < 2; mt++)
        #pragma unroll
        for (int nt = 0; nt < NT; nt++)
            #pragma unroll
            for (int j = 0; j < 4; j++) acc[mt][nt][j] = 0.f;

    load_chunk(0, 0);
    cp_commit();

    #pragma unroll 1
    for (int it = 0; it < KITER; it++) {
        if (it + 1 < KITER) {
            load_chunk(it + 1, (it + 1) & 1);
            cp_commit();
            cp_wait<1>();
        } else {
            cp_wait<0>();
        }
        __syncthreads();
        uint32_t sA  = sb + (it & 1) * STG;
        uint32_t sB  = sA + 2 * ASZ;
        #pragma unroll
        for (int ks = 0; ks < 2; ks++) {
            uint32_t ah[2][4], al_[2][4];
            #pragma unroll
            for (int mt = 0; mt < 2; mt++) {
                uint32_t ad = sA + ((warp_row * 32 + mt * 16 + (lane & 15)) * APITCH +
                                    ks * 16 + (lane >> 4) * 8) * 2;
                ldsm_x4(ah[mt], ad);
                ldsm_x4(al_[mt], ad + ASZ);
            }
            uint32_t bh[NT / 2][4], bl[NT / 2][4];
            #pragma unroll
            for (int p = 0; p < NT / 2; p++) {
                uint32_t bd = sB + ((ks * 16 + (lane & 15)) * BPITCH +
                                    warp_col * WN + p * 16 + (lane >> 4) * 8) * 2;
                ldsm_x4t(bh[p], bd);
                ldsm_x4t(bl[p], bd + BSZ);
            }
            #pragma unroll
            for (int mt = 0; mt < 2; mt++)
                #pragma unroll
                for (int nt = 0; nt < NT; nt++) {
                    const uint32_t* bhp = &bh[nt >> 1][(nt & 1) * 2];
                    const uint32_t* blp = &bl[nt >> 1][(nt & 1) * 2];
                    mma16816(acc[mt][nt], ah[mt], bhp);
                    mma16816(acc[mt][nt], ah[mt], blp);
                    mma16816(acc[mt][nt], al_[mt], bhp);
                }
        }
        __syncthreads();
    }

    // epilogue: bias (+mean fold) + leaky-relu + store
    const int lane4 = lane >> 2, lane2 = lane & 3;
    #pragma unroll
    for (int mt = 0; mt < 2; mt++) {
        int row0 = blockRow + warp_row * 32 + mt * 16 + lane4;
        #pragma unroll
        for (int nt = 0; nt < NT; nt++) {
            int col = warp_col * WN + nt * 8 + lane2 * 2;
            float b0, b1;
            if (NREL == 3) {
                b0 = (__ldg(&bias[col])     + __ldg(&bias[FD + col])     + __ldg(&bias[2 * FD + col]))     * (1.f / 3.f);
                b1 = (__ldg(&bias[col + 1]) + __ldg(&bias[FD + col + 1]) + __ldg(&bias[2 * FD + col + 1])) * (1.f / 3.f);
            } else {
                b0 = __ldg(&bias[col]);
                b1 = __ldg(&bias[col + 1]);
            }
            #pragma unroll
            for (int h = 0; h < 2; h++) {
                int row = row0 + h * 8;
                if (row < M) {
                    float v0 = acc[mt][nt][h * 2 + 0] + b0;
                    float v1 = acc[mt][nt][h * 2 + 1] + b1;
                    if (RELU) {
                        v0 = (v0 > 0.f) ? v0 : 0.01f * v0;
                        v1 = (v1 > 0.f) ? v1 : 0.01f * v1;
                    }
                    float2 v = {v0, v1};
                    *reinterpret_cast<float2*>(&C[(size_t)row * BN + col]) = v;
                }
            }
        }
    }
}

// ---------------- launch ----------------
extern "C" void kernel_launch(void* const* d_in, const int* in_sizes, int n_in,
                              void* d_out, int out_size) {
    const float* x    = (const float*)d_in[0];
    const int*   esrc = (const int*)  d_in[1];
    const int*   edst = (const int*)  d_in[2];
    const float* W0   = (const float*)d_in[3];
    const float* b0   = (const float*)d_in[4];
    const float* Wl   = (const float*)d_in[5];
    const float* bl   = (const float*)d_in[6];
    const float* Wout = (const float*)d_in[7];
    const float* bout = (const float*)d_in[8];
    float* out = (float*)d_out;

    void *p_cnt, *p_h0, *p_h1, *p_aggh, *p_aggl, *p_wh, *p_wl, *p_bf;
    cudaGetSymbolAddress(&p_cnt, g_cnt);
    cudaGetSymbolAddress(&p_h0, g_h0);
    cudaGetSymbolAddress(&p_h1, g_h1);
    cudaGetSymbolAddress(&p_aggh, g_aggh);
    cudaGetSymbolAddress(&p_aggl, g_aggl);
    cudaGetSymbolAddress(&p_wh, g_wh);
    cudaGetSymbolAddress(&p_wl, g_wl);
    cudaGetSymbolAddress(&p_bf, g_biasf);

    cudaFuncSetAttribute(k_mgemm<128, 12, 3, true >, cudaFuncAttributeMaxDynamicSharedMemorySize, 75776);
    cudaFuncSetAttribute(k_mgemm<64,  12, 1, false>, cudaFuncAttributeMaxDynamicSharedMemorySize, 59392);

    cudaMemsetAsync(p_cnt, 0, sizeof(int) * 2 * RR * NN);
    k_wprep<<<(WHID + 255) / 256, 256>>>(W0, Wl);
    k_wfuse<<<(WFUSE + OUTD + 255) / 256, 256>>>(Wl, Wout, bl, bout);

    dim3 gd((EE / 4 + 255) / 256, RR);
    k_degree<<<gd, 256>>>((const int4*)esrc, (const int4*)edst);
    dim3 gsn(NB, RR);
    k_scan1<<<gsn, 1024>>>();
    k_scan2<<<1, 32>>>();
    k_scan3<<<gsn, 1024>>>();
    dim3 ge((EE + 255) / 256, RR);
    k_fill<<<ge, 256>>>(esrc, edst);

    float4* hbuf[2] = { (float4*)p_h0, (float4*)p_h1 };
    uint2* aggh = (uint2*)p_aggh;
    uint2* aggl = (uint2*)p_aggl;
    const __nv_bfloat16* wh = (const __nv_bfloat16*)p_wh;
    const __nv_bfloat16* wl = (const __nv_bfloat16*)p_wl;

    dim3 gs((NN + 7) / 8, RR);
    const int GB = (NN + 127) / 128;   // 391

    const float4* cur = (const float4*)x;
    for (int l = 0; l < 4; l++) {
        k_spmm<<<gs, 256>>>(cur, aggh, aggl);
        const float* b = (l == 0) ? b0 : (bl + (size_t)(l - 1) * RR * FD);
        float* hout = (float*)hbuf[l & 1];
        k_mgemm<128, 12, 3, true><<<GB, 512, 75776>>>(
            (const __nv_bfloat16*)aggh, (const __nv_bfloat16*)aggl,
            wh + (size_t)l * WLAYER, wl + (size_t)l * WLAYER, b,
            hout, NN);
        cur = (const float4*)hout;
    }

    // layer 4 fused with final Linear: out = agg @ (W4cat @ Wout) + biasf
    k_spmm<<<gs, 256>>>(cur, aggh, aggl);
    k_mgemm<64, 12, 1, false><<<GB, 512, 59392>>>(
        (const __nv_bfloat16*)aggh, (const __nv_bfloat16*)aggl,
        wh + WHID, wl + WHID, (const float*)p_bf,
        out, NN);
}